// round 2
// baseline (speedup 1.0000x reference)
#include <cuda_runtime.h>
#include <cuda_bf16.h>
#include <math.h>

// Problem constants
constexpr int B_  = 2;
constexpr int T_  = 2048;
constexpr int C_  = 768;
constexpr int H_  = 12;
constexpr int NLEFT = 6;
constexpr int D_  = 64;
constexpr int QKV_N = 3 * C_;   // 2304
constexpr int M_  = B_ * T_;    // 4096

// Scratch (static device allocations are allowed)
__device__ float g_qkv[(size_t)B_ * T_ * QKV_N];  // (B,T,3,H,D) row-major = GEMM output
__device__ float g_ctx[(size_t)B_ * T_ * C_];     // (B,T,H,D)

// ---------------------------------------------------------------------------
// SGEMM (TN): C[m,n] = sum_k A[m,k] * B[n,k] + bias[n]
// A: M x K row-major, B: N x K row-major. BM=BN=128, BK=8, 256 thr, 8x8 micro.
// All dims divide tiles exactly for our shapes (M=4096, N in {2304,768}, K=768).
// ---------------------------------------------------------------------------
__global__ __launch_bounds__(256) void sgemm_tn_bias(
    const float* __restrict__ A, const float* __restrict__ Bm,
    const float* __restrict__ bias, float* __restrict__ C,
    int M, int N, int K)
{
    __shared__ float As[8][128];
    __shared__ float Bs[8][128];

    const int bm = blockIdx.y * 128;
    const int bn = blockIdx.x * 128;
    const int tid = threadIdx.x;

    const int tr = (tid >> 4) << 3;   // 0..120, step 8 (M rows)
    const int tc = (tid & 15) << 3;   // 0..120, step 8 (N cols)

    const int lrow = tid >> 1;        // 0..127
    const int lcol = (tid & 1) << 2;  // 0 or 4

    float acc[8][8];
#pragma unroll
    for (int i = 0; i < 8; i++)
#pragma unroll
        for (int j = 0; j < 8; j++) acc[i][j] = 0.f;

    const float* Aptr = A + (size_t)(bm + lrow) * K + lcol;
    const float* Bptr = Bm + (size_t)(bn + lrow) * K + lcol;

    for (int k0 = 0; k0 < K; k0 += 8) {
        float4 av = *(const float4*)(Aptr + k0);
        float4 bv = *(const float4*)(Bptr + k0);
        __syncthreads();
        As[lcol + 0][lrow] = av.x;
        As[lcol + 1][lrow] = av.y;
        As[lcol + 2][lrow] = av.z;
        As[lcol + 3][lrow] = av.w;
        Bs[lcol + 0][lrow] = bv.x;
        Bs[lcol + 1][lrow] = bv.y;
        Bs[lcol + 2][lrow] = bv.z;
        Bs[lcol + 3][lrow] = bv.w;
        __syncthreads();
#pragma unroll
        for (int k = 0; k < 8; k++) {
            float ar[8], br[8];
            *(float4*)&ar[0] = *(const float4*)&As[k][tr];
            *(float4*)&ar[4] = *(const float4*)&As[k][tr + 4];
            *(float4*)&br[0] = *(const float4*)&Bs[k][tc];
            *(float4*)&br[4] = *(const float4*)&Bs[k][tc + 4];
#pragma unroll
            for (int i = 0; i < 8; i++)
#pragma unroll
                for (int j = 0; j < 8; j++)
                    acc[i][j] += ar[i] * br[j];
        }
    }

    // epilogue: add bias, store
    float bb[8];
#pragma unroll
    for (int j = 0; j < 8; j++) bb[j] = bias[bn + tc + j];

#pragma unroll
    for (int i = 0; i < 8; i++) {
        float* crow = C + (size_t)(bm + tr + i) * N + bn + tc;
        float4 v0, v1;
        v0.x = acc[i][0] + bb[0]; v0.y = acc[i][1] + bb[1];
        v0.z = acc[i][2] + bb[2]; v0.w = acc[i][3] + bb[3];
        v1.x = acc[i][4] + bb[4]; v1.y = acc[i][5] + bb[5];
        v1.z = acc[i][6] + bb[6]; v1.w = acc[i][7] + bb[7];
        *(float4*)(crow)     = v0;
        *(float4*)(crow + 4) = v1;
    }
}

// ---------------------------------------------------------------------------
// Flash attention, fp32. One query per thread, 128 queries per block.
// qkv layout: [b, t, which(3), h, d] row-major (= QKV GEMM output).
// Heads h < NLEFT: causal (k <= q). Heads h >= NLEFT: anti-causal (k >= q).
// attention_mask: masked keys excluded (exp -> 0); equivalent to reference
// whenever any key in a row is valid (always true for the bench inputs).
// ---------------------------------------------------------------------------
__global__ __launch_bounds__(128) void attn_kernel(
    const float* __restrict__ qkv, const int* __restrict__ amask,
    float* __restrict__ ctx)
{
    const int b = blockIdx.z;
    const int h = blockIdx.y;
    const int q = blockIdx.x * 128 + threadIdx.x;
    const bool left = (h < NLEFT);

    __shared__ float Ks[32][64];
    __shared__ float Vs[32][64];
    __shared__ float Mv[32];

    float qreg[64];
    {
        const float* qp = qkv + ((size_t)(b * T_ + q)) * QKV_N + h * D_;
#pragma unroll
        for (int d = 0; d < 64; d += 4) {
            float4 v = *(const float4*)(qp + d);
            qreg[d]     = v.x * 0.125f;   // * D^-0.5
            qreg[d + 1] = v.y * 0.125f;
            qreg[d + 2] = v.z * 0.125f;
            qreg[d + 3] = v.w * 0.125f;
        }
    }
    float acc[64];
#pragma unroll
    for (int d = 0; d < 64; d++) acc[d] = 0.f;
    float m = -INFINITY, l = 0.f;

    const int kstart = left ? 0 : blockIdx.x * 128;
    const int kend   = left ? (blockIdx.x * 128 + 128) : T_;

    for (int c0 = kstart; c0 < kend; c0 += 32) {
        __syncthreads();
        {
            const float* kb = qkv + ((size_t)(b * T_ + c0)) * QKV_N + C_ + h * D_;
            const float* vb = kb + C_;
#pragma unroll
            for (int u = 0; u < 4; u++) {
                int idx = threadIdx.x + u * 128;  // 0..511
                int row = idx >> 4;
                int col = (idx & 15) << 2;
                *(float4*)&Ks[row][col] = *(const float4*)(kb + (size_t)row * QKV_N + col);
                *(float4*)&Vs[row][col] = *(const float4*)(vb + (size_t)row * QKV_N + col);
            }
            if (threadIdx.x < 32)
                Mv[threadIdx.x] = (float)amask[b * T_ + c0 + threadIdx.x];
        }
        __syncthreads();

        // per-thread chunk relevance (all threads still hit the loop-top barrier)
        const bool active = left ? (c0 <= q) : (c0 + 31 >= q);
        if (!active) continue;

        float sbuf[32];
        float cm = -INFINITY;
#pragma unroll 4
        for (int j = 0; j < 32; j++) {
            const int jg = c0 + j;
            const bool ok = (Mv[j] != 0.f) && (left ? (jg <= q) : (jg >= q));
            float s0 = 0.f, s1 = 0.f, s2 = 0.f, s3 = 0.f;
#pragma unroll
            for (int d = 0; d < 64; d += 4) {
                float4 kv = *(const float4*)&Ks[j][d];
                s0 += qreg[d]     * kv.x;
                s1 += qreg[d + 1] * kv.y;
                s2 += qreg[d + 2] * kv.z;
                s3 += qreg[d + 3] * kv.w;
            }
            float s = ok ? ((s0 + s1) + (s2 + s3)) : -INFINITY;
            sbuf[j] = s;
            cm = fmaxf(cm, s);
        }
        if (cm == -INFINITY) continue;  // nothing valid in chunk for this thread

        const float mnew = fmaxf(m, cm);
        const float corr = __expf(m - mnew);  // m == -inf -> 0
        l *= corr;
#pragma unroll
        for (int d = 0; d < 64; d++) acc[d] *= corr;
        m = mnew;

#pragma unroll 4
        for (int j = 0; j < 32; j++) {
            const float p = __expf(sbuf[j] - mnew);  // -inf -> 0
            l += p;
#pragma unroll
            for (int d = 0; d < 64; d += 4) {
                float4 vv = *(const float4*)&Vs[j][d];
                acc[d]     += p * vv.x;
                acc[d + 1] += p * vv.y;
                acc[d + 2] += p * vv.z;
                acc[d + 3] += p * vv.w;
            }
        }
    }

    const float inv = (l > 0.f) ? (1.f / l) : 0.f;
    float* op = ctx + ((size_t)(b * T_ + q)) * C_ + h * D_;
#pragma unroll
    for (int d = 0; d < 64; d += 4) {
        float4 v;
        v.x = acc[d] * inv;
        v.y = acc[d + 1] * inv;
        v.z = acc[d + 2] * inv;
        v.w = acc[d + 3] * inv;
        *(float4*)(op + d) = v;
    }
}

// ---------------------------------------------------------------------------
extern "C" void kernel_launch(void* const* d_in, const int* in_sizes, int n_in,
                              void* d_out, int out_size)
{
    (void)in_sizes; (void)n_in; (void)out_size;
    const float* x     = (const float*)d_in[0];
    const int*   amask = (const int*)d_in[1];
    const float* wqkv  = (const float*)d_in[2];
    const float* bqkv  = (const float*)d_in[3];
    const float* wo    = (const float*)d_in[4];
    const float* bo    = (const float*)d_in[5];
    float* out = (float*)d_out;

    float *qkv, *ctx;
    cudaGetSymbolAddress((void**)&qkv, g_qkv);
    cudaGetSymbolAddress((void**)&ctx, g_ctx);

    // 1) QKV projection: (4096 x 768) @ (768 x 2304)^T + b
    sgemm_tn_bias<<<dim3(QKV_N / 128, M_ / 128), 256>>>(
        x, wqkv, bqkv, qkv, M_, QKV_N, C_);

    // 2) Dual-direction flash attention
    attn_kernel<<<dim3(T_ / 128, H_, B_), 128>>>(qkv, amask, ctx);

    // 3) Output projection: (4096 x 768) @ (768 x 768)^T + b
    sgemm_tn_bias<<<dim3(C_ / 128, M_ / 128), 256>>>(
        ctx, wo, bo, out, M_, C_, C_);
}

// round 5
// speedup vs baseline: 1.3601x; 1.3601x over previous
#include <cuda_runtime.h>
#include <cuda_bf16.h>
#include <math.h>
#include <cstdint>

// Problem constants
constexpr int B_  = 2;
constexpr int T_  = 2048;
constexpr int C_  = 768;
constexpr int H_  = 12;
constexpr int NLEFT = 6;
constexpr int D_  = 64;
constexpr int QKV_N = 3 * C_;   // 2304
constexpr int M_  = B_ * T_;    // 4096

// Scratch (static device allocations are allowed)
__device__ float g_qkv[(size_t)B_ * T_ * QKV_N];  // (B,T,3,H,D) row-major
__device__ float g_ctx[(size_t)B_ * T_ * C_];     // (B,T,H,D)

__device__ __forceinline__ uint32_t f2tf(float f) {
    uint32_t r;
    asm("cvt.rna.tf32.f32 %0, %1;" : "=r"(r) : "f"(f));
    return r;
}

// ---------------------------------------------------------------------------
// TF32 tensor-core GEMM via mma.sync (TN): C[m,n] = sum_k A[m,k]*W[n,k] + bias[n]
// Block tile 128x128, BK=32, 256 threads = 8 warps, warp tile 64x32
// (4x4 atoms of m16n8k8). Requires M%128==0, N%128==0, K%32==0.
// ---------------------------------------------------------------------------
constexpr int BK = 32;

__global__ void __launch_bounds__(256) sgemm_mma(
    const float* __restrict__ A, const float* __restrict__ W,
    const float* __restrict__ bias, float* __restrict__ Cout,
    int M, int N, int K)
{
    // [m][k] and [n][k], padded to 36 words/row -> conflict-free frag loads
    __shared__ uint32_t As[128][36];
    __shared__ uint32_t Bs[128][36];

    const int tid  = threadIdx.x;
    const int wid  = tid >> 5;
    const int lane = tid & 31;
    const int wm   = wid & 1;        // warp row  (0..1) -> 64 rows
    const int wn   = wid >> 1;       // warp col  (0..3) -> 32 cols
    const int gid  = lane >> 2;      // 0..7
    const int tid4 = lane & 3;       // 0..3

    const int bm = blockIdx.y * 128;
    const int bn = blockIdx.x * 128;

    float acc[4][4][4];
#pragma unroll
    for (int mi = 0; mi < 4; mi++)
#pragma unroll
        for (int ni = 0; ni < 4; ni++)
#pragma unroll
            for (int r = 0; r < 4; r++) acc[mi][ni][r] = 0.f;

    // staging address for this thread (same each chunk)
    const int srow = tid >> 3;              // 0..31  (x4 iters -> 0..127)
    const int sc4  = (tid & 7) << 2;        // 0,4,...,28

    const int nch = K / BK;
    float4 pav[4], pwv[4];

    // prologue: prefetch chunk 0
#pragma unroll
    for (int u = 0; u < 4; u++) {
        const int row = srow + u * 32;
        pav[u] = *(const float4*)(A + (size_t)(bm + row) * K + sc4);
        pwv[u] = *(const float4*)(W + (size_t)(bn + row) * K + sc4);
    }

    for (int ch = 0; ch < nch; ++ch) {
        if (ch > 0) __syncthreads();   // prior compute done before overwrite

        // store prefetched chunk (fp32 -> tf32)
#pragma unroll
        for (int u = 0; u < 4; u++) {
            const int row = srow + u * 32;
            uint4 at, wt;
            at.x = f2tf(pav[u].x); at.y = f2tf(pav[u].y);
            at.z = f2tf(pav[u].z); at.w = f2tf(pav[u].w);
            wt.x = f2tf(pwv[u].x); wt.y = f2tf(pwv[u].y);
            wt.z = f2tf(pwv[u].z); wt.w = f2tf(pwv[u].w);
            *(uint4*)&As[row][sc4] = at;
            *(uint4*)&Bs[row][sc4] = wt;
        }
        __syncthreads();

        // prefetch next chunk (overlaps with MMA below)
        if (ch + 1 < nch) {
            const int koff = (ch + 1) * BK;
#pragma unroll
            for (int u = 0; u < 4; u++) {
                const int row = srow + u * 32;
                pav[u] = *(const float4*)(A + (size_t)(bm + row) * K + koff + sc4);
                pwv[u] = *(const float4*)(W + (size_t)(bn + row) * K + koff + sc4);
            }
        }

        // compute: 4 k-steps of 8, 16 atoms each
#pragma unroll
        for (int ks = 0; ks < 4; ks++) {
            const int k0 = ks * 8;
            uint32_t af[4][4], bf[4][2];
#pragma unroll
            for (int mi = 0; mi < 4; mi++) {
                const int row = wm * 64 + mi * 16 + gid;
                af[mi][0] = As[row][k0 + tid4];
                af[mi][1] = As[row + 8][k0 + tid4];
                af[mi][2] = As[row][k0 + tid4 + 4];
                af[mi][3] = As[row + 8][k0 + tid4 + 4];
            }
#pragma unroll
            for (int ni = 0; ni < 4; ni++) {
                const int col = wn * 32 + ni * 8 + gid;
                bf[ni][0] = Bs[col][k0 + tid4];
                bf[ni][1] = Bs[col][k0 + tid4 + 4];
            }
#pragma unroll
            for (int mi = 0; mi < 4; mi++)
#pragma unroll
                for (int ni = 0; ni < 4; ni++) {
                    asm volatile(
                        "mma.sync.aligned.m16n8k8.row.col.f32.tf32.tf32.f32 "
                        "{%0,%1,%2,%3}, {%4,%5,%6,%7}, {%8,%9}, {%0,%1,%2,%3};"
                        : "+f"(acc[mi][ni][0]), "+f"(acc[mi][ni][1]),
                          "+f"(acc[mi][ni][2]), "+f"(acc[mi][ni][3])
                        : "r"(af[mi][0]), "r"(af[mi][1]),
                          "r"(af[mi][2]), "r"(af[mi][3]),
                          "r"(bf[ni][0]), "r"(bf[ni][1]));
                }
        }
    }

    // epilogue: c0,c1 -> (gid, 2*tid4 / +1); c2,c3 -> (gid+8, same cols)
#pragma unroll
    for (int ni = 0; ni < 4; ni++) {
        const int col0 = bn + wn * 32 + ni * 8 + 2 * tid4;
        const float b0 = bias[col0], b1 = bias[col0 + 1];
#pragma unroll
        for (int mi = 0; mi < 4; mi++) {
            const int row0 = bm + wm * 64 + mi * 16 + gid;
            float2 v0, v1;
            v0.x = acc[mi][ni][0] + b0; v0.y = acc[mi][ni][1] + b1;
            v1.x = acc[mi][ni][2] + b0; v1.y = acc[mi][ni][3] + b1;
            *(float2*)(Cout + (size_t)row0 * N + col0)       = v0;
            *(float2*)(Cout + (size_t)(row0 + 8) * N + col0) = v1;
        }
    }
}

// ---------------------------------------------------------------------------
// Flash attention, fp32 (unchanged — next round's target).
// ---------------------------------------------------------------------------
__global__ __launch_bounds__(128) void attn_kernel(
    const float* __restrict__ qkv, const int* __restrict__ amask,
    float* __restrict__ ctx)
{
    const int b = blockIdx.z;
    const int h = blockIdx.y;
    const int q = blockIdx.x * 128 + threadIdx.x;
    const bool left = (h < NLEFT);

    __shared__ float Ks[32][64];
    __shared__ float Vs[32][64];
    __shared__ float Mv[32];

    float qreg[64];
    {
        const float* qp = qkv + ((size_t)(b * T_ + q)) * QKV_N + h * D_;
#pragma unroll
        for (int d = 0; d < 64; d += 4) {
            float4 v = *(const float4*)(qp + d);
            qreg[d]     = v.x * 0.125f;   // * D^-0.5
            qreg[d + 1] = v.y * 0.125f;
            qreg[d + 2] = v.z * 0.125f;
            qreg[d + 3] = v.w * 0.125f;
        }
    }
    float acc[64];
#pragma unroll
    for (int d = 0; d < 64; d++) acc[d] = 0.f;
    float m = -INFINITY, l = 0.f;

    const int kstart = left ? 0 : blockIdx.x * 128;
    const int kend   = left ? (blockIdx.x * 128 + 128) : T_;

    for (int c0 = kstart; c0 < kend; c0 += 32) {
        __syncthreads();
        {
            const float* kb = qkv + ((size_t)(b * T_ + c0)) * QKV_N + C_ + h * D_;
            const float* vb = kb + C_;
#pragma unroll
            for (int u = 0; u < 4; u++) {
                int idx = threadIdx.x + u * 128;  // 0..511
                int row = idx >> 4;
                int col = (idx & 15) << 2;
                *(float4*)&Ks[row][col] = *(const float4*)(kb + (size_t)row * QKV_N + col);
                *(float4*)&Vs[row][col] = *(const float4*)(vb + (size_t)row * QKV_N + col);
            }
            if (threadIdx.x < 32)
                Mv[threadIdx.x] = (float)amask[b * T_ + c0 + threadIdx.x];
        }
        __syncthreads();

        const bool active = left ? (c0 <= q) : (c0 + 31 >= q);
        if (!active) continue;

        float sbuf[32];
        float cm = -INFINITY;
#pragma unroll 4
        for (int j = 0; j < 32; j++) {
            const int jg = c0 + j;
            const bool ok = (Mv[j] != 0.f) && (left ? (jg <= q) : (jg >= q));
            float s0 = 0.f, s1 = 0.f, s2 = 0.f, s3 = 0.f;
#pragma unroll
            for (int d = 0; d < 64; d += 4) {
                float4 kv = *(const float4*)&Ks[j][d];
                s0 += qreg[d]     * kv.x;
                s1 += qreg[d + 1] * kv.y;
                s2 += qreg[d + 2] * kv.z;
                s3 += qreg[d + 3] * kv.w;
            }
            float s = ok ? ((s0 + s1) + (s2 + s3)) : -INFINITY;
            sbuf[j] = s;
            cm = fmaxf(cm, s);
        }
        if (cm == -INFINITY) continue;

        const float mnew = fmaxf(m, cm);
        const float corr = __expf(m - mnew);
        l *= corr;
#pragma unroll
        for (int d = 0; d < 64; d++) acc[d] *= corr;
        m = mnew;

#pragma unroll 4
        for (int j = 0; j < 32; j++) {
            const float p = __expf(sbuf[j] - mnew);
            l += p;
#pragma unroll
            for (int d = 0; d < 64; d += 4) {
                float4 vv = *(const float4*)&Vs[j][d];
                acc[d]     += p * vv.x;
                acc[d + 1] += p * vv.y;
                acc[d + 2] += p * vv.z;
                acc[d + 3] += p * vv.w;
            }
        }
    }

    const float inv = (l > 0.f) ? (1.f / l) : 0.f;
    float* op = ctx + ((size_t)(b * T_ + q)) * C_ + h * D_;
#pragma unroll
    for (int d = 0; d < 64; d += 4) {
        float4 v;
        v.x = acc[d] * inv;
        v.y = acc[d + 1] * inv;
        v.z = acc[d + 2] * inv;
        v.w = acc[d + 3] * inv;
        *(float4*)(op + d) = v;
    }
}

// ---------------------------------------------------------------------------
extern "C" void kernel_launch(void* const* d_in, const int* in_sizes, int n_in,
                              void* d_out, int out_size)
{
    (void)in_sizes; (void)n_in; (void)out_size;
    const float* x     = (const float*)d_in[0];
    const int*   amask = (const int*)d_in[1];
    const float* wqkv  = (const float*)d_in[2];
    const float* bqkv  = (const float*)d_in[3];
    const float* wo    = (const float*)d_in[4];
    const float* bo    = (const float*)d_in[5];
    float* out = (float*)d_out;

    float *qkv, *ctx;
    cudaGetSymbolAddress((void**)&qkv, g_qkv);
    cudaGetSymbolAddress((void**)&ctx, g_ctx);

    // 1) QKV projection: (4096 x 768) @ (768 x 2304)^T + b   [tf32 mma.sync]
    sgemm_mma<<<dim3(QKV_N / 128, M_ / 128), 256>>>(
        x, wqkv, bqkv, qkv, M_, QKV_N, C_);

    // 2) Dual-direction flash attention (fp32 SIMT)
    attn_kernel<<<dim3(T_ / 128, H_, B_), 128>>>(qkv, amask, ctx);

    // 3) Output projection: (4096 x 768) @ (768 x 768)^T + b [tf32 mma.sync]
    sgemm_mma<<<dim3(C_ / 128, M_ / 128), 256>>>(
        ctx, wo, bo, out, M_, C_, C_);
}

// round 6
// speedup vs baseline: 3.3710x; 2.4785x over previous
#include <cuda_runtime.h>
#include <cuda_bf16.h>
#include <math.h>
#include <cstdint>

// Problem constants
constexpr int B_  = 2;
constexpr int T_  = 2048;
constexpr int C_  = 768;
constexpr int H_  = 12;
constexpr int NLEFT = 6;
constexpr int D_  = 64;
constexpr int QKV_N = 3 * C_;   // 2304
constexpr int M_  = B_ * T_;    // 4096

// Scratch (static device allocations are allowed)
__device__ float g_qkv[(size_t)B_ * T_ * QKV_N];  // (B,T,3,H,D) row-major
__device__ float g_ctx[(size_t)B_ * T_ * C_];     // (B,T,H,D)

__device__ __forceinline__ uint32_t f2tf(float f) {
    uint32_t r;
    asm("cvt.rna.tf32.f32 %0, %1;" : "=r"(r) : "f"(f));
    return r;
}

#define MMA_TF32(d, a0, a1, a2, a3, b0, b1) \
    asm volatile( \
        "mma.sync.aligned.m16n8k8.row.col.f32.tf32.tf32.f32 " \
        "{%0,%1,%2,%3}, {%4,%5,%6,%7}, {%8,%9}, {%0,%1,%2,%3};" \
        : "+f"((d)[0]), "+f"((d)[1]), "+f"((d)[2]), "+f"((d)[3]) \
        : "r"(a0), "r"(a1), "r"(a2), "r"(a3), "r"(b0), "r"(b1))

// ---------------------------------------------------------------------------
// TF32 tensor-core GEMM via mma.sync (TN): C[m,n] = sum_k A[m,k]*W[n,k] + bias[n]
// (unchanged from round 4 — passed at 118us/QKV)
// ---------------------------------------------------------------------------
constexpr int BK = 32;

__global__ void __launch_bounds__(256) sgemm_mma(
    const float* __restrict__ A, const float* __restrict__ W,
    const float* __restrict__ bias, float* __restrict__ Cout,
    int M, int N, int K)
{
    __shared__ uint32_t As[128][36];
    __shared__ uint32_t Bs[128][36];

    const int tid  = threadIdx.x;
    const int wid  = tid >> 5;
    const int lane = tid & 31;
    const int wm   = wid & 1;
    const int wn   = wid >> 1;
    const int gid  = lane >> 2;
    const int tid4 = lane & 3;

    const int bm = blockIdx.y * 128;
    const int bn = blockIdx.x * 128;

    float acc[4][4][4];
#pragma unroll
    for (int mi = 0; mi < 4; mi++)
#pragma unroll
        for (int ni = 0; ni < 4; ni++)
#pragma unroll
            for (int r = 0; r < 4; r++) acc[mi][ni][r] = 0.f;

    const int srow = tid >> 3;
    const int sc4  = (tid & 7) << 2;

    const int nch = K / BK;
    float4 pav[4], pwv[4];

#pragma unroll
    for (int u = 0; u < 4; u++) {
        const int row = srow + u * 32;
        pav[u] = *(const float4*)(A + (size_t)(bm + row) * K + sc4);
        pwv[u] = *(const float4*)(W + (size_t)(bn + row) * K + sc4);
    }

    for (int ch = 0; ch < nch; ++ch) {
        if (ch > 0) __syncthreads();

#pragma unroll
        for (int u = 0; u < 4; u++) {
            const int row = srow + u * 32;
            uint4 at, wt;
            at.x = f2tf(pav[u].x); at.y = f2tf(pav[u].y);
            at.z = f2tf(pav[u].z); at.w = f2tf(pav[u].w);
            wt.x = f2tf(pwv[u].x); wt.y = f2tf(pwv[u].y);
            wt.z = f2tf(pwv[u].z); wt.w = f2tf(pwv[u].w);
            *(uint4*)&As[row][sc4] = at;
            *(uint4*)&Bs[row][sc4] = wt;
        }
        __syncthreads();

        if (ch + 1 < nch) {
            const int koff = (ch + 1) * BK;
#pragma unroll
            for (int u = 0; u < 4; u++) {
                const int row = srow + u * 32;
                pav[u] = *(const float4*)(A + (size_t)(bm + row) * K + koff + sc4);
                pwv[u] = *(const float4*)(W + (size_t)(bn + row) * K + koff + sc4);
            }
        }

#pragma unroll
        for (int ks = 0; ks < 4; ks++) {
            const int k0 = ks * 8;
            uint32_t af[4][4], bf[4][2];
#pragma unroll
            for (int mi = 0; mi < 4; mi++) {
                const int row = wm * 64 + mi * 16 + gid;
                af[mi][0] = As[row][k0 + tid4];
                af[mi][1] = As[row + 8][k0 + tid4];
                af[mi][2] = As[row][k0 + tid4 + 4];
                af[mi][3] = As[row + 8][k0 + tid4 + 4];
            }
#pragma unroll
            for (int ni = 0; ni < 4; ni++) {
                const int col = wn * 32 + ni * 8 + gid;
                bf[ni][0] = Bs[col][k0 + tid4];
                bf[ni][1] = Bs[col][k0 + tid4 + 4];
            }
#pragma unroll
            for (int mi = 0; mi < 4; mi++)
#pragma unroll
                for (int ni = 0; ni < 4; ni++)
                    MMA_TF32(acc[mi][ni], af[mi][0], af[mi][1], af[mi][2],
                             af[mi][3], bf[ni][0], bf[ni][1]);
        }
    }

#pragma unroll
    for (int ni = 0; ni < 4; ni++) {
        const int col0 = bn + wn * 32 + ni * 8 + 2 * tid4;
        const float b0 = bias[col0], b1 = bias[col0 + 1];
#pragma unroll
        for (int mi = 0; mi < 4; mi++) {
            const int row0 = bm + wm * 64 + mi * 16 + gid;
            float2 v0, v1;
            v0.x = acc[mi][ni][0] + b0; v0.y = acc[mi][ni][1] + b1;
            v1.x = acc[mi][ni][2] + b0; v1.y = acc[mi][ni][3] + b1;
            *(float2*)(Cout + (size_t)row0 * N + col0)       = v0;
            *(float2*)(Cout + (size_t)(row0 + 8) * N + col0) = v1;
        }
    }
}

// ---------------------------------------------------------------------------
// Tensor-core flash attention (tf32 mma.sync).
// Block: 64 queries x 1 head. 4 warps, 16 query rows each. 32-key chunks.
// Heads h < NLEFT: causal (k <= q). Heads h >= NLEFT: anti-causal (k >= q).
// ---------------------------------------------------------------------------
__global__ __launch_bounds__(128) void attn_mma(
    const float* __restrict__ qkv, const int* __restrict__ amask,
    float* __restrict__ ctx)
{
    // strides: 68,36 == 4 (mod 32); 72 == 8 (mod 32) -> conflict-free frags
    __shared__ uint32_t Qs[64][68];   // tf32 Q (pre-scaled)
    __shared__ uint32_t Ks[32][68];   // tf32 K chunk
    __shared__ uint32_t Vs[32][72];   // tf32 V chunk
    __shared__ uint32_t Ps[64][36];   // tf32 P (per-warp-private rows)
    __shared__ float Mv[32];

    const int b = blockIdx.z, h = blockIdx.y;
    const int q0 = blockIdx.x * 64;
    const bool left = (h < NLEFT);
    const int tid = threadIdx.x, wid = tid >> 5, lane = tid & 31;
    const int gid = lane >> 2, tid4 = lane & 3;

    // stage Q (64 x 64), scaled by D^-0.5
    {
        const float* qp = qkv + ((size_t)(b * T_ + q0)) * QKV_N + h * D_;
        for (int i = tid; i < 64 * 16; i += 128) {
            const int row = i >> 4, c4 = (i & 15) << 2;
            const float4 v = *(const float4*)(qp + (size_t)row * QKV_N + c4);
            Qs[row][c4 + 0] = f2tf(v.x * 0.125f);
            Qs[row][c4 + 1] = f2tf(v.y * 0.125f);
            Qs[row][c4 + 2] = f2tf(v.z * 0.125f);
            Qs[row][c4 + 3] = f2tf(v.w * 0.125f);
        }
    }

    float m0 = -1e30f, m1 = -1e30f, l0 = 0.f, l1 = 0.f;
    float acc[8][4];
#pragma unroll
    for (int ni = 0; ni < 8; ni++)
#pragma unroll
        for (int r = 0; r < 4; r++) acc[ni][r] = 0.f;

    const int r0  = wid * 16 + gid;   // local row in Qs/Ps
    const int gq0 = q0 + r0;          // global query row (c0/c1)
    const int gq1 = gq0 + 8;          // global query row (c2/c3)

    const int cbeg = left ? 0 : q0;
    const int cend = left ? (q0 + 64) : T_;

    for (int c0 = cbeg; c0 < cend; c0 += 32) {
        __syncthreads();
        {
            const float* kb = qkv + ((size_t)(b * T_ + c0)) * QKV_N + C_ + h * D_;
            for (int i = tid; i < 32 * 16; i += 128) {
                const int row = i >> 4, c4 = (i & 15) << 2;
                const float4 kv = *(const float4*)(kb + (size_t)row * QKV_N + c4);
                const float4 vv = *(const float4*)(kb + C_ + (size_t)row * QKV_N + c4);
                Ks[row][c4 + 0] = f2tf(kv.x); Ks[row][c4 + 1] = f2tf(kv.y);
                Ks[row][c4 + 2] = f2tf(kv.z); Ks[row][c4 + 3] = f2tf(kv.w);
                Vs[row][c4 + 0] = f2tf(vv.x); Vs[row][c4 + 1] = f2tf(vv.y);
                Vs[row][c4 + 2] = f2tf(vv.z); Vs[row][c4 + 3] = f2tf(vv.w);
            }
            if (tid < 32) Mv[tid] = (float)amask[b * T_ + c0 + tid];
        }
        __syncthreads();

        // warp-granular chunk relevance (barriers above stay uniform)
        const int qwlo = q0 + wid * 16, qwhi = qwlo + 15;
        const bool active = left ? (c0 <= qwhi) : (c0 + 31 >= qwlo);
        if (!active) continue;

        // S = Q K^T  (16 x 32 per warp)
        float s[4][4];
#pragma unroll
        for (int ni = 0; ni < 4; ni++)
#pragma unroll
            for (int r = 0; r < 4; r++) s[ni][r] = 0.f;
#pragma unroll
        for (int ks = 0; ks < 8; ks++) {
            const int k0 = ks * 8;
            const uint32_t a0 = Qs[r0][k0 + tid4];
            const uint32_t a1 = Qs[r0 + 8][k0 + tid4];
            const uint32_t a2 = Qs[r0][k0 + tid4 + 4];
            const uint32_t a3 = Qs[r0 + 8][k0 + tid4 + 4];
#pragma unroll
            for (int ni = 0; ni < 4; ni++) {
                const uint32_t b0 = Ks[ni * 8 + gid][k0 + tid4];
                const uint32_t b1 = Ks[ni * 8 + gid][k0 + tid4 + 4];
                MMA_TF32(s[ni], a0, a1, a2, a3, b0, b1);
            }
        }

        // mask + per-row chunk max (row lanes = quad)
        float cm0 = -1e30f, cm1 = -1e30f;
#pragma unroll
        for (int ni = 0; ni < 4; ni++) {
            const int kl = ni * 8 + 2 * tid4;
            const int kg = c0 + kl;
            const bool mv0 = (Mv[kl] != 0.f), mv1 = (Mv[kl + 1] != 0.f);
            const bool ok00 = mv0 && (left ? kg     <= gq0 : kg     >= gq0);
            const bool ok01 = mv1 && (left ? kg + 1 <= gq0 : kg + 1 >= gq0);
            const bool ok10 = mv0 && (left ? kg     <= gq1 : kg     >= gq1);
            const bool ok11 = mv1 && (left ? kg + 1 <= gq1 : kg + 1 >= gq1);
            s[ni][0] = ok00 ? s[ni][0] : -1e30f;
            s[ni][1] = ok01 ? s[ni][1] : -1e30f;
            s[ni][2] = ok10 ? s[ni][2] : -1e30f;
            s[ni][3] = ok11 ? s[ni][3] : -1e30f;
            cm0 = fmaxf(cm0, fmaxf(s[ni][0], s[ni][1]));
            cm1 = fmaxf(cm1, fmaxf(s[ni][2], s[ni][3]));
        }
        cm0 = fmaxf(cm0, __shfl_xor_sync(0xffffffffu, cm0, 1));
        cm0 = fmaxf(cm0, __shfl_xor_sync(0xffffffffu, cm0, 2));
        cm1 = fmaxf(cm1, __shfl_xor_sync(0xffffffffu, cm1, 1));
        cm1 = fmaxf(cm1, __shfl_xor_sync(0xffffffffu, cm1, 2));

        const float mn0 = fmaxf(m0, cm0), mn1 = fmaxf(m1, cm1);
        const float corr0 = __expf(m0 - mn0), corr1 = __expf(m1 - mn1);
        m0 = mn0; m1 = mn1;

        float rl0 = 0.f, rl1 = 0.f;
#pragma unroll
        for (int ni = 0; ni < 4; ni++) {
            const float p00 = __expf(s[ni][0] - mn0);
            const float p01 = __expf(s[ni][1] - mn0);
            const float p10 = __expf(s[ni][2] - mn1);
            const float p11 = __expf(s[ni][3] - mn1);
            rl0 += p00 + p01; rl1 += p10 + p11;
            uint2 u0, u1;
            u0.x = f2tf(p00); u0.y = f2tf(p01);
            u1.x = f2tf(p10); u1.y = f2tf(p11);
            *(uint2*)&Ps[r0][ni * 8 + 2 * tid4]     = u0;
            *(uint2*)&Ps[r0 + 8][ni * 8 + 2 * tid4] = u1;
        }
        rl0 += __shfl_xor_sync(0xffffffffu, rl0, 1);
        rl0 += __shfl_xor_sync(0xffffffffu, rl0, 2);
        rl1 += __shfl_xor_sync(0xffffffffu, rl1, 1);
        rl1 += __shfl_xor_sync(0xffffffffu, rl1, 2);
        l0 = l0 * corr0 + rl0;
        l1 = l1 * corr1 + rl1;

#pragma unroll
        for (int ni = 0; ni < 8; ni++) {
            acc[ni][0] *= corr0; acc[ni][1] *= corr0;
            acc[ni][2] *= corr1; acc[ni][3] *= corr1;
        }
        __syncwarp();   // P stores visible warp-wide before A-frag loads

        // O += P V  (16 x 64 per warp, k = 32 keys)
#pragma unroll
        for (int ks = 0; ks < 4; ks++) {
            const int k0 = ks * 8;
            const uint32_t a0 = Ps[r0][k0 + tid4];
            const uint32_t a1 = Ps[r0 + 8][k0 + tid4];
            const uint32_t a2 = Ps[r0][k0 + tid4 + 4];
            const uint32_t a3 = Ps[r0 + 8][k0 + tid4 + 4];
#pragma unroll
            for (int ni = 0; ni < 8; ni++) {
                const uint32_t b0 = Vs[k0 + tid4][ni * 8 + gid];
                const uint32_t b1 = Vs[k0 + tid4 + 4][ni * 8 + gid];
                MMA_TF32(acc[ni], a0, a1, a2, a3, b0, b1);
            }
        }
    }

    const float inv0 = (l0 > 0.f) ? (1.f / l0) : 0.f;
    const float inv1 = (l1 > 0.f) ? (1.f / l1) : 0.f;
    float* op0 = ctx + ((size_t)(b * T_ + gq0)) * C_ + h * D_;
    float* op1 = ctx + ((size_t)(b * T_ + gq1)) * C_ + h * D_;
#pragma unroll
    for (int ni = 0; ni < 8; ni++) {
        const int col = ni * 8 + 2 * tid4;
        float2 v0, v1;
        v0.x = acc[ni][0] * inv0; v0.y = acc[ni][1] * inv0;
        v1.x = acc[ni][2] * inv1; v1.y = acc[ni][3] * inv1;
        *(float2*)(op0 + col) = v0;
        *(float2*)(op1 + col) = v1;
    }
}

// ---------------------------------------------------------------------------
extern "C" void kernel_launch(void* const* d_in, const int* in_sizes, int n_in,
                              void* d_out, int out_size)
{
    (void)in_sizes; (void)n_in; (void)out_size;
    const float* x     = (const float*)d_in[0];
    const int*   amask = (const int*)d_in[1];
    const float* wqkv  = (const float*)d_in[2];
    const float* bqkv  = (const float*)d_in[3];
    const float* wo    = (const float*)d_in[4];
    const float* bo    = (const float*)d_in[5];
    float* out = (float*)d_out;

    float *qkv, *ctx;
    cudaGetSymbolAddress((void**)&qkv, g_qkv);
    cudaGetSymbolAddress((void**)&ctx, g_ctx);

    // 1) QKV projection: (4096 x 768) @ (768 x 2304)^T + b   [tf32 mma.sync]
    sgemm_mma<<<dim3(QKV_N / 128, M_ / 128), 256>>>(
        x, wqkv, bqkv, qkv, M_, QKV_N, C_);

    // 2) Dual-direction flash attention [tf32 mma.sync]
    attn_mma<<<dim3(T_ / 64, H_, B_), 128>>>(qkv, amask, ctx);

    // 3) Output projection: (4096 x 768) @ (768 x 768)^T + b [tf32 mma.sync]
    sgemm_mma<<<dim3(C_ / 128, M_ / 128), 256>>>(
        ctx, wo, bo, out, M_, C_, C_);
}

// round 7
// speedup vs baseline: 3.5202x; 1.0443x over previous
#include <cuda_runtime.h>
#include <cuda_bf16.h>
#include <math.h>
#include <cstdint>

// Problem constants
constexpr int B_  = 2;
constexpr int T_  = 2048;
constexpr int C_  = 768;
constexpr int H_  = 12;
constexpr int NLEFT = 6;
constexpr int D_  = 64;
constexpr int QKV_N = 3 * C_;   // 2304
constexpr int M_  = B_ * T_;    // 4096

// Scratch (static device allocations are allowed)
__device__ float g_qkv[(size_t)B_ * T_ * QKV_N];  // (B,T,3,H,D) row-major
__device__ float g_ctx[(size_t)B_ * T_ * C_];     // (B,T,H,D)

__device__ __forceinline__ uint32_t f2tf(float f) {
    uint32_t r;
    asm("cvt.rna.tf32.f32 %0, %1;" : "=r"(r) : "f"(f));
    return r;
}

#define MMA_TF32(d, a0, a1, a2, a3, b0, b1) \
    asm volatile( \
        "mma.sync.aligned.m16n8k8.row.col.f32.tf32.tf32.f32 " \
        "{%0,%1,%2,%3}, {%4,%5,%6,%7}, {%8,%9}, {%0,%1,%2,%3};" \
        : "+f"((d)[0]), "+f"((d)[1]), "+f"((d)[2]), "+f"((d)[3]) \
        : "r"(a0), "r"(a1), "r"(a2), "r"(a3), "r"(b0), "r"(b1))

// ---------------------------------------------------------------------------
// TF32 tensor-core GEMM via mma.sync (TN), double-buffered smem.
// C[m,n] = sum_k A[m,k]*W[n,k] + bias[n]
// Block 128x128, BK=32, 256 threads = 8 warps, warp tile 64x32.
// ---------------------------------------------------------------------------
constexpr int BK = 32;
constexpr int GEMM_BUF_W  = 128 * 36 * 2;          // A + B, words, per buffer
constexpr int GEMM_SMEM_B = 2 * GEMM_BUF_W * 4;    // 73728 bytes

__global__ void __launch_bounds__(256) sgemm_mma(
    const float* __restrict__ A, const float* __restrict__ W,
    const float* __restrict__ bias, float* __restrict__ Cout,
    int M, int N, int K)
{
    extern __shared__ uint32_t sm[];
    // buffer b: As = sm + b*GEMM_BUF_W, Bs = As + 128*36

    const int tid  = threadIdx.x;
    const int wid  = tid >> 5;
    const int lane = tid & 31;
    const int wm   = wid & 1;
    const int wn   = wid >> 1;
    const int gid  = lane >> 2;
    const int tid4 = lane & 3;

    const int bm = blockIdx.y * 128;
    const int bn = blockIdx.x * 128;

    float acc[4][4][4];
#pragma unroll
    for (int mi = 0; mi < 4; mi++)
#pragma unroll
        for (int ni = 0; ni < 4; ni++)
#pragma unroll
            for (int r = 0; r < 4; r++) acc[mi][ni][r] = 0.f;

    const int srow = tid >> 3;          // 0..31 (+u*32)
    const int sc4  = (tid & 7) << 2;    // 0,4,...,28

    const int nch = K / BK;
    float4 pav[4], pwv[4];

    // prologue: stage chunk 0 into buffer 0
#pragma unroll
    for (int u = 0; u < 4; u++) {
        const int row = srow + u * 32;
        pav[u] = *(const float4*)(A + (size_t)(bm + row) * K + sc4);
        pwv[u] = *(const float4*)(W + (size_t)(bn + row) * K + sc4);
    }
    {
        uint32_t* As0 = sm;
        uint32_t* Bs0 = sm + 128 * 36;
#pragma unroll
        for (int u = 0; u < 4; u++) {
            const int row = srow + u * 32;
            uint4 at, wt;
            at.x = f2tf(pav[u].x); at.y = f2tf(pav[u].y);
            at.z = f2tf(pav[u].z); at.w = f2tf(pav[u].w);
            wt.x = f2tf(pwv[u].x); wt.y = f2tf(pwv[u].y);
            wt.z = f2tf(pwv[u].z); wt.w = f2tf(pwv[u].w);
            *(uint4*)&As0[row * 36 + sc4] = at;
            *(uint4*)&Bs0[row * 36 + sc4] = wt;
        }
    }
    __syncthreads();

    for (int ch = 0; ch < nch; ++ch) {
        const int cur = ch & 1;
        const bool have_next = (ch + 1 < nch);

        // issue next chunk's global loads (latency hidden by MMAs below)
        if (have_next) {
            const int koff = (ch + 1) * BK;
#pragma unroll
            for (int u = 0; u < 4; u++) {
                const int row = srow + u * 32;
                pav[u] = *(const float4*)(A + (size_t)(bm + row) * K + koff + sc4);
                pwv[u] = *(const float4*)(W + (size_t)(bn + row) * K + koff + sc4);
            }
        }

        // compute on current buffer
        const uint32_t* Acur = sm + cur * GEMM_BUF_W;
        const uint32_t* Bcur = Acur + 128 * 36;
#pragma unroll
        for (int ks = 0; ks < 4; ks++) {
            const int k0 = ks * 8;
            uint32_t af[4][4], bf[4][2];
#pragma unroll
            for (int mi = 0; mi < 4; mi++) {
                const int row = wm * 64 + mi * 16 + gid;
                af[mi][0] = Acur[row * 36 + k0 + tid4];
                af[mi][1] = Acur[(row + 8) * 36 + k0 + tid4];
                af[mi][2] = Acur[row * 36 + k0 + tid4 + 4];
                af[mi][3] = Acur[(row + 8) * 36 + k0 + tid4 + 4];
            }
#pragma unroll
            for (int ni = 0; ni < 4; ni++) {
                const int col = wn * 32 + ni * 8 + gid;
                bf[ni][0] = Bcur[col * 36 + k0 + tid4];
                bf[ni][1] = Bcur[col * 36 + k0 + tid4 + 4];
            }
#pragma unroll
            for (int mi = 0; mi < 4; mi++)
#pragma unroll
                for (int ni = 0; ni < 4; ni++)
                    MMA_TF32(acc[mi][ni], af[mi][0], af[mi][1], af[mi][2],
                             af[mi][3], bf[ni][0], bf[ni][1]);
        }

        // store next chunk into the other buffer (overlaps tensor pipe drain)
        if (have_next) {
            uint32_t* An = sm + (cur ^ 1) * GEMM_BUF_W;
            uint32_t* Bn = An + 128 * 36;
#pragma unroll
            for (int u = 0; u < 4; u++) {
                const int row = srow + u * 32;
                uint4 at, wt;
                at.x = f2tf(pav[u].x); at.y = f2tf(pav[u].y);
                at.z = f2tf(pav[u].z); at.w = f2tf(pav[u].w);
                wt.x = f2tf(pwv[u].x); wt.y = f2tf(pwv[u].y);
                wt.z = f2tf(pwv[u].z); wt.w = f2tf(pwv[u].w);
                *(uint4*)&An[row * 36 + sc4] = at;
                *(uint4*)&Bn[row * 36 + sc4] = wt;
            }
        }
        __syncthreads();
    }

#pragma unroll
    for (int ni = 0; ni < 4; ni++) {
        const int col0 = bn + wn * 32 + ni * 8 + 2 * tid4;
        const float b0 = bias[col0], b1 = bias[col0 + 1];
#pragma unroll
        for (int mi = 0; mi < 4; mi++) {
            const int row0 = bm + wm * 64 + mi * 16 + gid;
            float2 v0, v1;
            v0.x = acc[mi][ni][0] + b0; v0.y = acc[mi][ni][1] + b1;
            v1.x = acc[mi][ni][2] + b0; v1.y = acc[mi][ni][3] + b1;
            *(float2*)(Cout + (size_t)row0 * N + col0)       = v0;
            *(float2*)(Cout + (size_t)(row0 + 8) * N + col0) = v1;
        }
    }
}

// ---------------------------------------------------------------------------
// Tensor-core flash attention (tf32 mma.sync), double-buffered K/V staging.
// Block: 64 queries x 1 head. 4 warps, 16 query rows each. 32-key chunks.
// ---------------------------------------------------------------------------
// dynamic smem word offsets
constexpr int QS_OFF = 0;                   // 64 x 68
constexpr int PS_OFF = QS_OFF + 64 * 68;    // 64 x 36
constexpr int KS_OFF = PS_OFF + 64 * 36;    // 2 x (32 x 68)
constexpr int KS_SZ  = 32 * 68;
constexpr int VS_OFF = KS_OFF + 2 * KS_SZ;  // 2 x (32 x 72)
constexpr int VS_SZ  = 32 * 72;
constexpr int MV_OFF = VS_OFF + 2 * VS_SZ;  // 2 x 32 (float)
constexpr int ATTN_SMEM_B = (MV_OFF + 64) * 4;   // 62720 bytes

__global__ void __launch_bounds__(128) attn_mma(
    const float* __restrict__ qkv, const int* __restrict__ amask,
    float* __restrict__ ctx)
{
    extern __shared__ uint32_t sm[];
    float* smf = (float*)sm;

    const int b = blockIdx.z, h = blockIdx.y;
    const int q0 = blockIdx.x * 64;
    const bool left = (h < NLEFT);
    const int tid = threadIdx.x, wid = tid >> 5, lane = tid & 31;
    const int gid = lane >> 2, tid4 = lane & 3;

    // stage Q (64 x 64), scaled by D^-0.5
    {
        const float* qp = qkv + ((size_t)(b * T_ + q0)) * QKV_N + h * D_;
        for (int i = tid; i < 64 * 16; i += 128) {
            const int row = i >> 4, c4 = (i & 15) << 2;
            const float4 v = *(const float4*)(qp + (size_t)row * QKV_N + c4);
            sm[QS_OFF + row * 68 + c4 + 0] = f2tf(v.x * 0.125f);
            sm[QS_OFF + row * 68 + c4 + 1] = f2tf(v.y * 0.125f);
            sm[QS_OFF + row * 68 + c4 + 2] = f2tf(v.z * 0.125f);
            sm[QS_OFF + row * 68 + c4 + 3] = f2tf(v.w * 0.125f);
        }
    }

    float m0 = -1e30f, m1 = -1e30f, l0 = 0.f, l1 = 0.f;
    float acc[8][4];
#pragma unroll
    for (int ni = 0; ni < 8; ni++)
#pragma unroll
        for (int r = 0; r < 4; r++) acc[ni][r] = 0.f;

    const int r0  = wid * 16 + gid;
    const int gq0 = q0 + r0;
    const int gq1 = gq0 + 8;

    const int cbeg = left ? 0 : q0;
    const int cend = left ? (q0 + 64) : T_;

    // K/V chunk prefetch registers
    float4 kreg[4], vreg[4];
    int mreg = 1;
    const int prow = tid >> 4;            // 0..7 (+u*8)
    const int pc4  = (tid & 15) << 2;     // 0,4,...,60

    auto prefetch = [&](int c0) {
        const float* kb = qkv + ((size_t)(b * T_ + c0)) * QKV_N + C_ + h * D_;
#pragma unroll
        for (int u = 0; u < 4; u++) {
            const int row = prow + u * 8;
            kreg[u] = *(const float4*)(kb + (size_t)row * QKV_N + pc4);
            vreg[u] = *(const float4*)(kb + C_ + (size_t)row * QKV_N + pc4);
        }
        if (tid < 32) mreg = amask[b * T_ + c0 + tid];
    };
    auto store_buf = [&](int bf) {
        uint32_t* Kb = sm + KS_OFF + bf * KS_SZ;
        uint32_t* Vb = sm + VS_OFF + bf * VS_SZ;
#pragma unroll
        for (int u = 0; u < 4; u++) {
            const int row = prow + u * 8;
            Kb[row * 68 + pc4 + 0] = f2tf(kreg[u].x);
            Kb[row * 68 + pc4 + 1] = f2tf(kreg[u].y);
            Kb[row * 68 + pc4 + 2] = f2tf(kreg[u].z);
            Kb[row * 68 + pc4 + 3] = f2tf(kreg[u].w);
            Vb[row * 72 + pc4 + 0] = f2tf(vreg[u].x);
            Vb[row * 72 + pc4 + 1] = f2tf(vreg[u].y);
            Vb[row * 72 + pc4 + 2] = f2tf(vreg[u].z);
            Vb[row * 72 + pc4 + 3] = f2tf(vreg[u].w);
        }
        if (tid < 32) smf[MV_OFF + bf * 32 + tid] = (float)mreg;
    };

    prefetch(cbeg);
    store_buf(0);
    __syncthreads();

    int buf = 0;
    for (int c0 = cbeg; c0 < cend; c0 += 32) {
        const bool have_next = (c0 + 32 < cend);
        if (have_next) prefetch(c0 + 32);

        // warp-granular chunk relevance
        const int qwlo = q0 + wid * 16, qwhi = qwlo + 15;
        const bool active = left ? (c0 <= qwhi) : (c0 + 31 >= qwlo);

        if (active) {
            const uint32_t* Kb = sm + KS_OFF + buf * KS_SZ;
            const uint32_t* Vb = sm + VS_OFF + buf * VS_SZ;
            const float*    Mb = smf + MV_OFF + buf * 32;

            // S = Q K^T  (16 x 32 per warp)
            float s[4][4];
#pragma unroll
            for (int ni = 0; ni < 4; ni++)
#pragma unroll
                for (int r = 0; r < 4; r++) s[ni][r] = 0.f;
#pragma unroll
            for (int ks = 0; ks < 8; ks++) {
                const int k0 = ks * 8;
                const uint32_t a0 = sm[QS_OFF + r0 * 68 + k0 + tid4];
                const uint32_t a1 = sm[QS_OFF + (r0 + 8) * 68 + k0 + tid4];
                const uint32_t a2 = sm[QS_OFF + r0 * 68 + k0 + tid4 + 4];
                const uint32_t a3 = sm[QS_OFF + (r0 + 8) * 68 + k0 + tid4 + 4];
#pragma unroll
                for (int ni = 0; ni < 4; ni++) {
                    const uint32_t b0 = Kb[(ni * 8 + gid) * 68 + k0 + tid4];
                    const uint32_t b1 = Kb[(ni * 8 + gid) * 68 + k0 + tid4 + 4];
                    MMA_TF32(s[ni], a0, a1, a2, a3, b0, b1);
                }
            }

            // mask + per-row chunk max (row lanes = quad)
            float cm0 = -1e30f, cm1 = -1e30f;
#pragma unroll
            for (int ni = 0; ni < 4; ni++) {
                const int kl = ni * 8 + 2 * tid4;
                const int kg = c0 + kl;
                const bool mv0 = (Mb[kl] != 0.f), mv1 = (Mb[kl + 1] != 0.f);
                const bool ok00 = mv0 && (left ? kg     <= gq0 : kg     >= gq0);
                const bool ok01 = mv1 && (left ? kg + 1 <= gq0 : kg + 1 >= gq0);
                const bool ok10 = mv0 && (left ? kg     <= gq1 : kg     >= gq1);
                const bool ok11 = mv1 && (left ? kg + 1 <= gq1 : kg + 1 >= gq1);
                s[ni][0] = ok00 ? s[ni][0] : -1e30f;
                s[ni][1] = ok01 ? s[ni][1] : -1e30f;
                s[ni][2] = ok10 ? s[ni][2] : -1e30f;
                s[ni][3] = ok11 ? s[ni][3] : -1e30f;
                cm0 = fmaxf(cm0, fmaxf(s[ni][0], s[ni][1]));
                cm1 = fmaxf(cm1, fmaxf(s[ni][2], s[ni][3]));
            }
            cm0 = fmaxf(cm0, __shfl_xor_sync(0xffffffffu, cm0, 1));
            cm0 = fmaxf(cm0, __shfl_xor_sync(0xffffffffu, cm0, 2));
            cm1 = fmaxf(cm1, __shfl_xor_sync(0xffffffffu, cm1, 1));
            cm1 = fmaxf(cm1, __shfl_xor_sync(0xffffffffu, cm1, 2));

            const float mn0 = fmaxf(m0, cm0), mn1 = fmaxf(m1, cm1);
            const float corr0 = __expf(m0 - mn0), corr1 = __expf(m1 - mn1);
            m0 = mn0; m1 = mn1;

            float rl0 = 0.f, rl1 = 0.f;
#pragma unroll
            for (int ni = 0; ni < 4; ni++) {
                const float p00 = __expf(s[ni][0] - mn0);
                const float p01 = __expf(s[ni][1] - mn0);
                const float p10 = __expf(s[ni][2] - mn1);
                const float p11 = __expf(s[ni][3] - mn1);
                rl0 += p00 + p01; rl1 += p10 + p11;
                uint2 u0, u1;
                u0.x = f2tf(p00); u0.y = f2tf(p01);
                u1.x = f2tf(p10); u1.y = f2tf(p11);
                *(uint2*)&sm[PS_OFF + r0 * 36 + ni * 8 + 2 * tid4]       = u0;
                *(uint2*)&sm[PS_OFF + (r0 + 8) * 36 + ni * 8 + 2 * tid4] = u1;
            }
            rl0 += __shfl_xor_sync(0xffffffffu, rl0, 1);
            rl0 += __shfl_xor_sync(0xffffffffu, rl0, 2);
            rl1 += __shfl_xor_sync(0xffffffffu, rl1, 1);
            rl1 += __shfl_xor_sync(0xffffffffu, rl1, 2);
            l0 = l0 * corr0 + rl0;
            l1 = l1 * corr1 + rl1;

#pragma unroll
            for (int ni = 0; ni < 8; ni++) {
                acc[ni][0] *= corr0; acc[ni][1] *= corr0;
                acc[ni][2] *= corr1; acc[ni][3] *= corr1;
            }
            __syncwarp();   // P stores visible warp-wide before A-frag loads

            // O += P V  (16 x 64 per warp, k = 32 keys)
#pragma unroll
            for (int ks = 0; ks < 4; ks++) {
                const int k0 = ks * 8;
                const uint32_t a0 = sm[PS_OFF + r0 * 36 + k0 + tid4];
                const uint32_t a1 = sm[PS_OFF + (r0 + 8) * 36 + k0 + tid4];
                const uint32_t a2 = sm[PS_OFF + r0 * 36 + k0 + tid4 + 4];
                const uint32_t a3 = sm[PS_OFF + (r0 + 8) * 36 + k0 + tid4 + 4];
#pragma unroll
                for (int ni = 0; ni < 8; ni++) {
                    const uint32_t b0 = Vb[(k0 + tid4) * 72 + ni * 8 + gid];
                    const uint32_t b1 = Vb[(k0 + tid4 + 4) * 72 + ni * 8 + gid];
                    MMA_TF32(acc[ni], a0, a1, a2, a3, b0, b1);
                }
            }
        }

        if (have_next) store_buf(buf ^ 1);
        __syncthreads();
        buf ^= 1;
    }

    const float inv0 = (l0 > 0.f) ? (1.f / l0) : 0.f;
    const float inv1 = (l1 > 0.f) ? (1.f / l1) : 0.f;
    float* op0 = ctx + ((size_t)(b * T_ + gq0)) * C_ + h * D_;
    float* op1 = ctx + ((size_t)(b * T_ + gq1)) * C_ + h * D_;
#pragma unroll
    for (int ni = 0; ni < 8; ni++) {
        const int col = ni * 8 + 2 * tid4;
        float2 v0, v1;
        v0.x = acc[ni][0] * inv0; v0.y = acc[ni][1] * inv0;
        v1.x = acc[ni][2] * inv1; v1.y = acc[ni][3] * inv1;
        *(float2*)(op0 + col) = v0;
        *(float2*)(op1 + col) = v1;
    }
}

// ---------------------------------------------------------------------------
extern "C" void kernel_launch(void* const* d_in, const int* in_sizes, int n_in,
                              void* d_out, int out_size)
{
    (void)in_sizes; (void)n_in; (void)out_size;
    const float* x     = (const float*)d_in[0];
    const int*   amask = (const int*)d_in[1];
    const float* wqkv  = (const float*)d_in[2];
    const float* bqkv  = (const float*)d_in[3];
    const float* wo    = (const float*)d_in[4];
    const float* bo    = (const float*)d_in[5];
    float* out = (float*)d_out;

    float *qkv, *ctx;
    cudaGetSymbolAddress((void**)&qkv, g_qkv);
    cudaGetSymbolAddress((void**)&ctx, g_ctx);

    cudaFuncSetAttribute(sgemm_mma, cudaFuncAttributeMaxDynamicSharedMemorySize,
                         GEMM_SMEM_B);
    cudaFuncSetAttribute(attn_mma, cudaFuncAttributeMaxDynamicSharedMemorySize,
                         ATTN_SMEM_B);

    // 1) QKV projection: (4096 x 768) @ (768 x 2304)^T + b   [tf32 mma.sync]
    sgemm_mma<<<dim3(QKV_N / 128, M_ / 128), 256, GEMM_SMEM_B>>>(
        x, wqkv, bqkv, qkv, M_, QKV_N, C_);

    // 2) Dual-direction flash attention [tf32 mma.sync]
    attn_mma<<<dim3(T_ / 64, H_, B_), 128, ATTN_SMEM_B>>>(qkv, amask, ctx);

    // 3) Output projection: (4096 x 768) @ (768 x 768)^T + b [tf32 mma.sync]
    sgemm_mma<<<dim3(C_ / 128, M_ / 128), 256, GEMM_SMEM_B>>>(
        ctx, wo, bo, out, M_, C_, C_);
}

// round 8
// speedup vs baseline: 3.5410x; 1.0059x over previous
#include <cuda_runtime.h>
#include <cuda_bf16.h>
#include <math.h>
#include <cstdint>

// Problem constants
constexpr int B_  = 2;
constexpr int T_  = 2048;
constexpr int C_  = 768;
constexpr int H_  = 12;
constexpr int NLEFT = 6;
constexpr int D_  = 64;
constexpr int QKV_N = 3 * C_;   // 2304
constexpr int M_  = B_ * T_;    // 4096

// Scratch (static device allocations are allowed)
__device__ float g_qkv[(size_t)B_ * T_ * QKV_N];  // (B,T,3,H,D) row-major
__device__ float g_ctx[(size_t)B_ * T_ * C_];     // (B,T,H,D)

__device__ __forceinline__ uint32_t f2tf(float f) {
    uint32_t r;
    asm("cvt.rna.tf32.f32 %0, %1;" : "=r"(r) : "f"(f));
    return r;
}

#define MMA_TF32(d, a0, a1, a2, a3, b0, b1) \
    asm volatile( \
        "mma.sync.aligned.m16n8k8.row.col.f32.tf32.tf32.f32 " \
        "{%0,%1,%2,%3}, {%4,%5,%6,%7}, {%8,%9}, {%0,%1,%2,%3};" \
        : "+f"((d)[0]), "+f"((d)[1]), "+f"((d)[2]), "+f"((d)[3]) \
        : "r"(a0), "r"(a1), "r"(a2), "r"(a3), "r"(b0), "r"(b1))

// Paired layout: within a 32-wide k-chunk, value k = ks*8+t is stored at
// column pos = ks*8 + (t&3)*2 + (t>>2), then XOR-swizzled by ((row&3)<<3).
// Fragment pair (k0+tid4, k0+tid4+4) -> adjacent words -> one LDS.64 at
// col = ((ks ^ (row&3))<<3) + tid4*2.   (conflict-free per half-warp phase)

// ---------------------------------------------------------------------------
// TF32 tensor-core GEMM via mma.sync (TN), double-buffered, paired layout.
// C[m,n] = sum_k A[m,k]*W[n,k] + bias[n]
// Block 128x128, BK=32, 256 threads = 8 warps, warp tile 64x32, 2 CTAs/SM.
// ---------------------------------------------------------------------------
constexpr int GBUF_W      = 128 * 32;              // words per tensor per buf
constexpr int GEMM_BUF_W  = 2 * GBUF_W;            // A + B per buffer
constexpr int GEMM_SMEM_B = 2 * GEMM_BUF_W * 4;    // 65536 bytes

__global__ void __launch_bounds__(256, 2) sgemm_mma(
    const float* __restrict__ A, const float* __restrict__ W,
    const float* __restrict__ bias, float* __restrict__ Cout,
    int M, int N, int K)
{
    extern __shared__ uint32_t sm[];

    const int tid  = threadIdx.x;
    const int wid  = tid >> 5;
    const int lane = tid & 31;
    const int wm   = wid & 1;
    const int wn   = wid >> 1;
    const int gid  = lane >> 2;
    const int tid4 = lane & 3;

    const int bm = blockIdx.y * 128;
    const int bn = blockIdx.x * 128;

    float acc[4][4][4];
#pragma unroll
    for (int mi = 0; mi < 4; mi++)
#pragma unroll
        for (int ni = 0; ni < 4; ni++)
#pragma unroll
            for (int r = 0; r < 4; r++) acc[mi][ni][r] = 0.f;

    // staging: thread -> (row = srow+u*32, quad j), k bases kb, kb+4
    const int srow = tid >> 3;                    // 0..31
    const int j    = tid & 7;
    const int kb   = (j >> 1) * 8 + (j & 1) * 2;  // gmem k offset in chunk
    const int scol = (j * 4) ^ ((srow & 3) << 3); // swizzled store column

    const int nch = K / 32;
    float2 pal[4], pah[4], pwl[4], pwh[4];

    auto gload = [&](int koff) {
#pragma unroll
        for (int u = 0; u < 4; u++) {
            const int row = srow + u * 32;
            const float* ap = A + (size_t)(bm + row) * K + koff + kb;
            const float* wp = W + (size_t)(bn + row) * K + koff + kb;
            pal[u] = *(const float2*)(ap);
            pah[u] = *(const float2*)(ap + 4);
            pwl[u] = *(const float2*)(wp);
            pwh[u] = *(const float2*)(wp + 4);
        }
    };
    auto sstore = [&](int buf) {
        uint32_t* Ab = sm + buf * GEMM_BUF_W;
        uint32_t* Bb = Ab + GBUF_W;
#pragma unroll
        for (int u = 0; u < 4; u++) {
            const int row = srow + u * 32;
            uint4 at, wt;
            at.x = f2tf(pal[u].x); at.y = f2tf(pah[u].x);
            at.z = f2tf(pal[u].y); at.w = f2tf(pah[u].y);
            wt.x = f2tf(pwl[u].x); wt.y = f2tf(pwh[u].x);
            wt.z = f2tf(pwl[u].y); wt.w = f2tf(pwh[u].y);
            *(uint4*)&Ab[row * 32 + scol] = at;
            *(uint4*)&Bb[row * 32 + scol] = wt;
        }
    };

    gload(0);
    sstore(0);
    __syncthreads();

    const int g3 = gid & 3;

    for (int ch = 0; ch < nch; ++ch) {
        const int cur = ch & 1;
        const bool have_next = (ch + 1 < nch);
        if (have_next) gload((ch + 1) * 32);

        const uint32_t* Acur = sm + cur * GEMM_BUF_W;
        const uint32_t* Bcur = Acur + GBUF_W;
#pragma unroll
        for (int ks = 0; ks < 4; ks++) {
            const int c = ((ks ^ g3) << 3) + tid4 * 2;
            uint2 aA[4], aB[4], bb[4];
#pragma unroll
            for (int mi = 0; mi < 4; mi++) {
                const int row = wm * 64 + mi * 16 + gid;
                aA[mi] = *(const uint2*)&Acur[row * 32 + c];
                aB[mi] = *(const uint2*)&Acur[(row + 8) * 32 + c];
            }
#pragma unroll
            for (int ni = 0; ni < 4; ni++) {
                const int col = wn * 32 + ni * 8 + gid;
                bb[ni] = *(const uint2*)&Bcur[col * 32 + c];
            }
#pragma unroll
            for (int mi = 0; mi < 4; mi++)
#pragma unroll
                for (int ni = 0; ni < 4; ni++)
                    MMA_TF32(acc[mi][ni], aA[mi].x, aB[mi].x, aA[mi].y,
                             aB[mi].y, bb[ni].x, bb[ni].y);
        }

        if (have_next) sstore(cur ^ 1);
        __syncthreads();
    }

#pragma unroll
    for (int ni = 0; ni < 4; ni++) {
        const int col0 = bn + wn * 32 + ni * 8 + 2 * tid4;
        const float b0 = bias[col0], b1 = bias[col0 + 1];
#pragma unroll
        for (int mi = 0; mi < 4; mi++) {
            const int row0 = bm + wm * 64 + mi * 16 + gid;
            float2 v0, v1;
            v0.x = acc[mi][ni][0] + b0; v0.y = acc[mi][ni][1] + b1;
            v1.x = acc[mi][ni][2] + b0; v1.y = acc[mi][ni][3] + b1;
            *(float2*)(Cout + (size_t)row0 * N + col0)       = v0;
            *(float2*)(Cout + (size_t)(row0 + 8) * N + col0) = v1;
        }
    }
}

// ---------------------------------------------------------------------------
// Tensor-core flash attention (tf32 mma.sync), paired Q/K layout,
// double-buffered K/V staging. Block: 64 queries x 1 head, 4 warps.
// ---------------------------------------------------------------------------
constexpr int QS_OFF = 0;                   // 64 x 64 paired-swizzled
constexpr int PS_OFF = QS_OFF + 64 * 64;    // 64 x 36
constexpr int KS_OFF = PS_OFF + 64 * 36;    // 2 x (32 x 64) paired-swizzled
constexpr int KS_SZ  = 32 * 64;
constexpr int VS_OFF = KS_OFF + 2 * KS_SZ;  // 2 x (32 x 72) key-major
constexpr int VS_SZ  = 32 * 72;
constexpr int MV_OFF = VS_OFF + 2 * VS_SZ;  // 2 x 32
constexpr int ATTN_SMEM_B = (MV_OFF + 64) * 4;   // 60672 bytes

__global__ void __launch_bounds__(128) attn_mma(
    const float* __restrict__ qkv, const int* __restrict__ amask,
    float* __restrict__ ctx)
{
    extern __shared__ uint32_t sm[];
    float* smf = (float*)sm;

    const int b = blockIdx.z, h = blockIdx.y;
    const int q0 = blockIdx.x * 64;
    const bool left = (h < NLEFT);
    const int tid = threadIdx.x, wid = tid >> 5, lane = tid & 31;
    const int gid = lane >> 2, tid4 = lane & 3;
    const int g3 = gid & 3;

    // stage Q (64 x 64) in paired-swizzled layout, scaled by D^-0.5
    {
        const float* qp = qkv + ((size_t)(b * T_ + q0)) * QKV_N + h * D_;
        for (int i = tid; i < 64 * 16; i += 128) {
            const int row = i >> 4, jq = i & 15;
            const int kq = (jq >> 1) * 8 + (jq & 1) * 2;
            const float* qr = qp + (size_t)row * QKV_N + kq;
            const float2 lo = *(const float2*)(qr);
            const float2 hi = *(const float2*)(qr + 4);
            const int col = (jq * 4) ^ ((row & 3) << 3);
            uint4 v;
            v.x = f2tf(lo.x * 0.125f); v.y = f2tf(hi.x * 0.125f);
            v.z = f2tf(lo.y * 0.125f); v.w = f2tf(hi.y * 0.125f);
            *(uint4*)&sm[QS_OFF + row * 64 + col] = v;
        }
    }

    float m0 = -1e30f, m1 = -1e30f, l0 = 0.f, l1 = 0.f;
    float acc[8][4];
#pragma unroll
    for (int ni = 0; ni < 8; ni++)
#pragma unroll
        for (int r = 0; r < 4; r++) acc[ni][r] = 0.f;

    const int r0  = wid * 16 + gid;
    const int gq0 = q0 + r0;
    const int gq1 = gq0 + 8;

    const int cbeg = left ? 0 : q0;
    const int cend = left ? (q0 + 64) : T_;

    // prefetch registers: K paired float2s, V float4s
    float2 klo[4], khi[4];
    float4 vreg[4];
    int mreg = 1;
    const int vrow = tid >> 4;            // 0..7 (+u*8)
    const int vc4  = (tid & 15) << 2;     // 0,4,...,60

    auto prefetch = [&](int c0) {
        const float* kb = qkv + ((size_t)(b * T_ + c0)) * QKV_N + C_ + h * D_;
#pragma unroll
        for (int u = 0; u < 4; u++) {
            const int idx = tid + u * 128;
            const int row = idx >> 4, jk = idx & 15;
            const int kk = (jk >> 1) * 8 + (jk & 1) * 2;
            const float* kr = kb + (size_t)row * QKV_N + kk;
            klo[u] = *(const float2*)(kr);
            khi[u] = *(const float2*)(kr + 4);
            const int rv = vrow + u * 8;
            vreg[u] = *(const float4*)(kb + C_ + (size_t)rv * QKV_N + vc4);
        }
        if (tid < 32) mreg = amask[b * T_ + c0 + tid];
    };
    auto store_buf = [&](int bf) {
        uint32_t* Kb = sm + KS_OFF + bf * KS_SZ;
        uint32_t* Vb = sm + VS_OFF + bf * VS_SZ;
#pragma unroll
        for (int u = 0; u < 4; u++) {
            const int idx = tid + u * 128;
            const int row = idx >> 4, jk = idx & 15;
            const int col = (jk * 4) ^ ((row & 3) << 3);
            uint4 kv;
            kv.x = f2tf(klo[u].x); kv.y = f2tf(khi[u].x);
            kv.z = f2tf(klo[u].y); kv.w = f2tf(khi[u].y);
            *(uint4*)&Kb[row * 64 + col] = kv;
            const int rv = vrow + u * 8;
            Vb[rv * 72 + vc4 + 0] = f2tf(vreg[u].x);
            Vb[rv * 72 + vc4 + 1] = f2tf(vreg[u].y);
            Vb[rv * 72 + vc4 + 2] = f2tf(vreg[u].z);
            Vb[rv * 72 + vc4 + 3] = f2tf(vreg[u].w);
        }
        if (tid < 32) smf[MV_OFF + bf * 32 + tid] = (float)mreg;
    };

    prefetch(cbeg);
    store_buf(0);
    __syncthreads();

    int buf = 0;
    for (int c0 = cbeg; c0 < cend; c0 += 32) {
        const bool have_next = (c0 + 32 < cend);
        if (have_next) prefetch(c0 + 32);

        const int qwlo = q0 + wid * 16, qwhi = qwlo + 15;
        const bool active = left ? (c0 <= qwhi) : (c0 + 31 >= qwlo);

        if (active) {
            const uint32_t* Kb = sm + KS_OFF + buf * KS_SZ;
            const uint32_t* Vb = sm + VS_OFF + buf * VS_SZ;
            const float*    Mb = smf + MV_OFF + buf * 32;

            // S = Q K^T  (16 x 32 per warp), paired LDS.64 frags
            float s[4][4];
#pragma unroll
            for (int ni = 0; ni < 4; ni++)
#pragma unroll
                for (int r = 0; r < 4; r++) s[ni][r] = 0.f;
#pragma unroll
            for (int ks = 0; ks < 8; ks++) {
                const int c = ((ks ^ g3) << 3) + tid4 * 2;
                const uint2 qa = *(const uint2*)&sm[QS_OFF + r0 * 64 + c];
                const uint2 qb = *(const uint2*)&sm[QS_OFF + (r0 + 8) * 64 + c];
#pragma unroll
                for (int ni = 0; ni < 4; ni++) {
                    const uint2 kf =
                        *(const uint2*)&Kb[(ni * 8 + gid) * 64 + c];
                    MMA_TF32(s[ni], qa.x, qb.x, qa.y, qb.y, kf.x, kf.y);
                }
            }

            // mask + per-row chunk max (row lanes = quad)
            float cm0 = -1e30f, cm1 = -1e30f;
#pragma unroll
            for (int ni = 0; ni < 4; ni++) {
                const int kl = ni * 8 + 2 * tid4;
                const int kg = c0 + kl;
                const bool mv0 = (Mb[kl] != 0.f), mv1 = (Mb[kl + 1] != 0.f);
                const bool ok00 = mv0 && (left ? kg     <= gq0 : kg     >= gq0);
                const bool ok01 = mv1 && (left ? kg + 1 <= gq0 : kg + 1 >= gq0);
                const bool ok10 = mv0 && (left ? kg     <= gq1 : kg     >= gq1);
                const bool ok11 = mv1 && (left ? kg + 1 <= gq1 : kg + 1 >= gq1);
                s[ni][0] = ok00 ? s[ni][0] : -1e30f;
                s[ni][1] = ok01 ? s[ni][1] : -1e30f;
                s[ni][2] = ok10 ? s[ni][2] : -1e30f;
                s[ni][3] = ok11 ? s[ni][3] : -1e30f;
                cm0 = fmaxf(cm0, fmaxf(s[ni][0], s[ni][1]));
                cm1 = fmaxf(cm1, fmaxf(s[ni][2], s[ni][3]));
            }
            cm0 = fmaxf(cm0, __shfl_xor_sync(0xffffffffu, cm0, 1));
            cm0 = fmaxf(cm0, __shfl_xor_sync(0xffffffffu, cm0, 2));
            cm1 = fmaxf(cm1, __shfl_xor_sync(0xffffffffu, cm1, 1));
            cm1 = fmaxf(cm1, __shfl_xor_sync(0xffffffffu, cm1, 2));

            const float mn0 = fmaxf(m0, cm0), mn1 = fmaxf(m1, cm1);
            const float corr0 = __expf(m0 - mn0), corr1 = __expf(m1 - mn1);
            m0 = mn0; m1 = mn1;

            float rl0 = 0.f, rl1 = 0.f;
#pragma unroll
            for (int ni = 0; ni < 4; ni++) {
                const float p00 = __expf(s[ni][0] - mn0);
                const float p01 = __expf(s[ni][1] - mn0);
                const float p10 = __expf(s[ni][2] - mn1);
                const float p11 = __expf(s[ni][3] - mn1);
                rl0 += p00 + p01; rl1 += p10 + p11;
                uint2 u0, u1;
                u0.x = f2tf(p00); u0.y = f2tf(p01);
                u1.x = f2tf(p10); u1.y = f2tf(p11);
                *(uint2*)&sm[PS_OFF + r0 * 36 + ni * 8 + 2 * tid4]       = u0;
                *(uint2*)&sm[PS_OFF + (r0 + 8) * 36 + ni * 8 + 2 * tid4] = u1;
            }
            rl0 += __shfl_xor_sync(0xffffffffu, rl0, 1);
            rl0 += __shfl_xor_sync(0xffffffffu, rl0, 2);
            rl1 += __shfl_xor_sync(0xffffffffu, rl1, 1);
            rl1 += __shfl_xor_sync(0xffffffffu, rl1, 2);
            l0 = l0 * corr0 + rl0;
            l1 = l1 * corr1 + rl1;

#pragma unroll
            for (int ni = 0; ni < 8; ni++) {
                acc[ni][0] *= corr0; acc[ni][1] *= corr0;
                acc[ni][2] *= corr1; acc[ni][3] *= corr1;
            }
            __syncwarp();   // P stores visible warp-wide before A-frag loads

            // O += P V  (16 x 64 per warp, k = 32 keys)
#pragma unroll
            for (int ks = 0; ks < 4; ks++) {
                const int k0 = ks * 8;
                const uint32_t a0 = sm[PS_OFF + r0 * 36 + k0 + tid4];
                const uint32_t a1 = sm[PS_OFF + (r0 + 8) * 36 + k0 + tid4];
                const uint32_t a2 = sm[PS_OFF + r0 * 36 + k0 + tid4 + 4];
                const uint32_t a3 = sm[PS_OFF + (r0 + 8) * 36 + k0 + tid4 + 4];
#pragma unroll
                for (int ni = 0; ni < 8; ni++) {
                    const uint32_t b0 = Vb[(k0 + tid4) * 72 + ni * 8 + gid];
                    const uint32_t b1 = Vb[(k0 + tid4 + 4) * 72 + ni * 8 + gid];
                    MMA_TF32(acc[ni], a0, a1, a2, a3, b0, b1);
                }
            }
        }

        if (have_next) store_buf(buf ^ 1);
        __syncthreads();
        buf ^= 1;
    }

    const float inv0 = (l0 > 0.f) ? (1.f / l0) : 0.f;
    const float inv1 = (l1 > 0.f) ? (1.f / l1) : 0.f;
    float* op0 = ctx + ((size_t)(b * T_ + gq0)) * C_ + h * D_;
    float* op1 = ctx + ((size_t)(b * T_ + gq1)) * C_ + h * D_;
#pragma unroll
    for (int ni = 0; ni < 8; ni++) {
        const int col = ni * 8 + 2 * tid4;
        float2 v0, v1;
        v0.x = acc[ni][0] * inv0; v0.y = acc[ni][1] * inv0;
        v1.x = acc[ni][2] * inv1; v1.y = acc[ni][3] * inv1;
        *(float2*)(op0 + col) = v0;
        *(float2*)(op1 + col) = v1;
    }
}

// ---------------------------------------------------------------------------
extern "C" void kernel_launch(void* const* d_in, const int* in_sizes, int n_in,
                              void* d_out, int out_size)
{
    (void)in_sizes; (void)n_in; (void)out_size;
    const float* x     = (const float*)d_in[0];
    const int*   amask = (const int*)d_in[1];
    const float* wqkv  = (const float*)d_in[2];
    const float* bqkv  = (const float*)d_in[3];
    const float* wo    = (const float*)d_in[4];
    const float* bo    = (const float*)d_in[5];
    float* out = (float*)d_out;

    float *qkv, *ctx;
    cudaGetSymbolAddress((void**)&qkv, g_qkv);
    cudaGetSymbolAddress((void**)&ctx, g_ctx);

    cudaFuncSetAttribute(sgemm_mma, cudaFuncAttributeMaxDynamicSharedMemorySize,
                         GEMM_SMEM_B);
    cudaFuncSetAttribute(attn_mma, cudaFuncAttributeMaxDynamicSharedMemorySize,
                         ATTN_SMEM_B);

    // 1) QKV projection: (4096 x 768) @ (768 x 2304)^T + b   [tf32 mma.sync]
    sgemm_mma<<<dim3(QKV_N / 128, M_ / 128), 256, GEMM_SMEM_B>>>(
        x, wqkv, bqkv, qkv, M_, QKV_N, C_);

    // 2) Dual-direction flash attention [tf32 mma.sync]
    attn_mma<<<dim3(T_ / 64, H_, B_), 128, ATTN_SMEM_B>>>(qkv, amask, ctx);

    // 3) Output projection: (4096 x 768) @ (768 x 768)^T + b [tf32 mma.sync]
    sgemm_mma<<<dim3(C_ / 128, M_ / 128), 256, GEMM_SMEM_B>>>(
        ctx, wo, bo, out, M_, C_, C_);
}